// round 1
// baseline (speedup 1.0000x reference)
#include <cuda_runtime.h>
#include <cstddef>

// Problem dims
#define MB   4096      // batch
#define DIN  4096      // input dim
#define HID  16384     // hidden
#define ONN  1000      // output nodes
#define K2   (DIN + HID)  // 20480

// Tiling
#define BM 128
#define BN 128
#define BK 16
#define TM 8
#define TN 8

// Scratch for h1 (4096 x 16384 fp32 = 256 MiB) — __device__ global, no alloc.
__device__ float g_h1[(size_t)MB * HID];

// ---------------------------------------------------------------------------
// GEMM1: C = relu(A @ B^T + bias)   A=x [M,K], B=W1 [N,K], C=g_h1 [M,N]
// M=4096, N=16384, K=4096
// ---------------------------------------------------------------------------
__global__ __launch_bounds__(256, 2)
void gemm1_relu(const float* __restrict__ A,
                const float* __restrict__ Bm,
                const float* __restrict__ bias)
{
    const int M = MB, N = HID, K = DIN;
    __shared__ float As[BK][BM + 4];
    __shared__ float Bs[BK][BN + 4];

    const int t   = threadIdx.x;
    const int m0  = blockIdx.y * BM;
    const int n0  = blockIdx.x * BN;
    const int ty  = t / 16;          // 0..15
    const int tx  = t % 16;          // 0..15
    const int lrow = t >> 2;         // 0..63
    const int lc4  = t & 3;          // 0..3  (which float4 in the 16-wide k slab)

    float acc[TM][TN];
    #pragma unroll
    for (int i = 0; i < TM; i++)
        #pragma unroll
        for (int j = 0; j < TN; j++) acc[i][j] = 0.0f;

    for (int k0 = 0; k0 < K; k0 += BK) {
        // Load A tile (128 rows x 16 k), transposed into As[k][m]
        #pragma unroll
        for (int r = 0; r < 2; r++) {
            const int row = lrow + r * 64;
            float4 v = *reinterpret_cast<const float4*>(
                &A[(size_t)(m0 + row) * K + k0 + lc4 * 4]);
            As[lc4 * 4 + 0][row] = v.x;
            As[lc4 * 4 + 1][row] = v.y;
            As[lc4 * 4 + 2][row] = v.z;
            As[lc4 * 4 + 3][row] = v.w;
        }
        // Load B tile (128 rows x 16 k), transposed into Bs[k][n]
        #pragma unroll
        for (int r = 0; r < 2; r++) {
            const int row = lrow + r * 64;
            float4 v = *reinterpret_cast<const float4*>(
                &Bm[(size_t)(n0 + row) * K + k0 + lc4 * 4]);
            Bs[lc4 * 4 + 0][row] = v.x;
            Bs[lc4 * 4 + 1][row] = v.y;
            Bs[lc4 * 4 + 2][row] = v.z;
            Bs[lc4 * 4 + 3][row] = v.w;
        }
        __syncthreads();

        #pragma unroll
        for (int k = 0; k < BK; k++) {
            float4 a0 = *reinterpret_cast<const float4*>(&As[k][ty * TM]);
            float4 a1 = *reinterpret_cast<const float4*>(&As[k][ty * TM + 4]);
            float4 b0 = *reinterpret_cast<const float4*>(&Bs[k][tx * TN]);
            float4 b1 = *reinterpret_cast<const float4*>(&Bs[k][tx * TN + 4]);
            float ra[TM] = {a0.x, a0.y, a0.z, a0.w, a1.x, a1.y, a1.z, a1.w};
            float rb[TN] = {b0.x, b0.y, b0.z, b0.w, b1.x, b1.y, b1.z, b1.w};
            #pragma unroll
            for (int i = 0; i < TM; i++)
                #pragma unroll
                for (int j = 0; j < TN; j++)
                    acc[i][j] += ra[i] * rb[j];
        }
        __syncthreads();
    }

    // Epilogue: bias + relu, vectorized stores
    float bv[TN];
    #pragma unroll
    for (int j = 0; j < TN; j++) bv[j] = bias[n0 + tx * TN + j];

    #pragma unroll
    for (int i = 0; i < TM; i++) {
        const int m = m0 + ty * TM + i;
        float4 o0, o1;
        float v;
        v = acc[i][0] + bv[0]; o0.x = v > 0.f ? v : 0.f;
        v = acc[i][1] + bv[1]; o0.y = v > 0.f ? v : 0.f;
        v = acc[i][2] + bv[2]; o0.z = v > 0.f ? v : 0.f;
        v = acc[i][3] + bv[3]; o0.w = v > 0.f ? v : 0.f;
        v = acc[i][4] + bv[4]; o1.x = v > 0.f ? v : 0.f;
        v = acc[i][5] + bv[5]; o1.y = v > 0.f ? v : 0.f;
        v = acc[i][6] + bv[6]; o1.z = v > 0.f ? v : 0.f;
        v = acc[i][7] + bv[7]; o1.w = v > 0.f ? v : 0.f;
        *reinterpret_cast<float4*>(&g_h1[(size_t)m * N + n0 + tx * TN])     = o0;
        *reinterpret_cast<float4*>(&g_h1[(size_t)m * N + n0 + tx * TN + 4]) = o1;
    }
}

// ---------------------------------------------------------------------------
// GEMM2: out = concat(x, h1) @ W2^T + b2
// M=4096, N=1000 (grid padded to 1024), K=20480 split (x: k<4096, h1: rest)
// ---------------------------------------------------------------------------
__global__ __launch_bounds__(256, 2)
void gemm2(const float* __restrict__ X,
           const float* __restrict__ W2,
           const float* __restrict__ b2,
           float* __restrict__ Out)
{
    const int M = MB, N = ONN, K = K2;
    __shared__ float As[BK][BM + 4];
    __shared__ float Bs[BK][BN + 4];

    const int t   = threadIdx.x;
    const int m0  = blockIdx.y * BM;
    const int n0  = blockIdx.x * BN;
    const int ty  = t / 16;
    const int tx  = t % 16;
    const int lrow = t >> 2;
    const int lc4  = t & 3;

    float acc[TM][TN];
    #pragma unroll
    for (int i = 0; i < TM; i++)
        #pragma unroll
        for (int j = 0; j < TN; j++) acc[i][j] = 0.0f;

    for (int k0 = 0; k0 < K; k0 += BK) {
        const int kk = k0 + lc4 * 4;
        // A tile: source is x for k<DIN, g_h1 afterwards (BK-tile never straddles)
        #pragma unroll
        for (int r = 0; r < 2; r++) {
            const int row = lrow + r * 64;
            float4 v;
            if (k0 < DIN) {
                v = *reinterpret_cast<const float4*>(
                    &X[(size_t)(m0 + row) * DIN + kk]);
            } else {
                v = *reinterpret_cast<const float4*>(
                    &g_h1[(size_t)(m0 + row) * HID + (kk - DIN)]);
            }
            As[lc4 * 4 + 0][row] = v.x;
            As[lc4 * 4 + 1][row] = v.y;
            As[lc4 * 4 + 2][row] = v.z;
            As[lc4 * 4 + 3][row] = v.w;
        }
        // B tile: guard rows >= 1000
        #pragma unroll
        for (int r = 0; r < 2; r++) {
            const int row = lrow + r * 64;
            const int nrow = n0 + row;
            float4 v = make_float4(0.f, 0.f, 0.f, 0.f);
            if (nrow < N) {
                v = *reinterpret_cast<const float4*>(
                    &W2[(size_t)nrow * K + kk]);
            }
            Bs[lc4 * 4 + 0][row] = v.x;
            Bs[lc4 * 4 + 1][row] = v.y;
            Bs[lc4 * 4 + 2][row] = v.z;
            Bs[lc4 * 4 + 3][row] = v.w;
        }
        __syncthreads();

        #pragma unroll
        for (int k = 0; k < BK; k++) {
            float4 a0 = *reinterpret_cast<const float4*>(&As[k][ty * TM]);
            float4 a1 = *reinterpret_cast<const float4*>(&As[k][ty * TM + 4]);
            float4 b0 = *reinterpret_cast<const float4*>(&Bs[k][tx * TN]);
            float4 b1 = *reinterpret_cast<const float4*>(&Bs[k][tx * TN + 4]);
            float ra[TM] = {a0.x, a0.y, a0.z, a0.w, a1.x, a1.y, a1.z, a1.w};
            float rb[TN] = {b0.x, b0.y, b0.z, b0.w, b1.x, b1.y, b1.z, b1.w};
            #pragma unroll
            for (int i = 0; i < TM; i++)
                #pragma unroll
                for (int j = 0; j < TN; j++)
                    acc[i][j] += ra[i] * rb[j];
        }
        __syncthreads();
    }

    #pragma unroll
    for (int i = 0; i < TM; i++) {
        const int m = m0 + ty * TM + i;
        #pragma unroll
        for (int j = 0; j < TN; j++) {
            const int n = n0 + tx * TN + j;
            if (n < N) {
                Out[(size_t)m * N + n] = acc[i][j] + b2[n];
            }
        }
    }
}

extern "C" void kernel_launch(void* const* d_in, const int* in_sizes, int n_in,
                              void* d_out, int out_size)
{
    const float* x  = (const float*)d_in[0];
    const float* W1 = (const float*)d_in[1];
    const float* b1 = (const float*)d_in[2];
    const float* W2 = (const float*)d_in[3];
    const float* b2 = (const float*)d_in[4];
    float* out = (float*)d_out;

    dim3 block(256);
    dim3 grid1(HID / BN, MB / BM);          // 128 x 32
    gemm1_relu<<<grid1, block>>>(x, W1, b1);

    dim3 grid2((ONN + BN - 1) / BN, MB / BM);  // 8 x 32
    gemm2<<<grid2, block>>>(x, W2, b2, out);
}

// round 3
// speedup vs baseline: 2.8942x; 2.8942x over previous
#include <cuda_runtime.h>
#include <cuda_bf16.h>
#include <cuda.h>
#include <cstdint>
#include <cstddef>

// ---------------- problem dims ----------------
#define MB_   4096
#define DIN_  4096
#define HID_  16384
#define ONN_  1000
#define K2_   (DIN_ + HID_)

// ---------------- tile config -----------------
#define BM 128
#define BN 128
#define KC 64                   // bf16 K per stage (128 B rows = SW128 atom)
#define STG_AH 0
#define STG_AL 16384
#define STG_BH 32768
#define STG_BL 49152
#define STAGE_SZ 65536
#define STAGE_BYTES 65536u
#define STAGE0_OFF 1024
#define SMEM_TOTAL (STAGE0_OFF + 2 * STAGE_SZ)   // 132096

// bf16 split scratch (static device arrays — no allocation)
__device__ __align__(1024) __nv_bfloat16 g_xh [(size_t)MB_ * DIN_];
__device__ __align__(1024) __nv_bfloat16 g_xl [(size_t)MB_ * DIN_];
__device__ __align__(1024) __nv_bfloat16 g_w1h[(size_t)HID_ * DIN_];
__device__ __align__(1024) __nv_bfloat16 g_w1l[(size_t)HID_ * DIN_];
__device__ __align__(1024) __nv_bfloat16 g_w2h[(size_t)ONN_ * K2_];
__device__ __align__(1024) __nv_bfloat16 g_w2l[(size_t)ONN_ * K2_];
__device__ __align__(1024) __nv_bfloat16 g_h1h[(size_t)MB_ * HID_];
__device__ __align__(1024) __nv_bfloat16 g_h1l[(size_t)MB_ * HID_];

// ---------------- PTX helpers ------------------
__device__ __forceinline__ uint32_t smem_u32(const void* p) {
    uint32_t a;
    asm("{ .reg .u64 t; cvta.to.shared.u64 t, %1; cvt.u32.u64 %0, t; }"
        : "=r"(a) : "l"(p));
    return a;
}

#define MBARRIER_INIT(addr, cnt) \
    asm volatile("mbarrier.init.shared.b64 [%0], %1;" :: "r"(addr), "r"(cnt) : "memory")

#define MBARRIER_EXPECT_TX(addr, bytes) \
    asm volatile("mbarrier.arrive.expect_tx.shared.b64 _, [%0], %1;" \
                 :: "r"(addr), "r"(bytes) : "memory")

#define MBARRIER_ARRIVE(addr) \
    asm volatile("mbarrier.arrive.shared.b64 _, [%0];" :: "r"(addr) : "memory")

#define MBARRIER_WAIT_PARITY(addr, parity) do {                                   \
    uint32_t _m = (addr); uint32_t _p = (parity); uint32_t _d;                    \
    asm volatile("{ .reg .pred p; mbarrier.try_wait.parity.acquire.cta.shared::cta.b64 p, [%1], %2; selp.b32 %0, 1, 0, p; }" \
        : "=r"(_d) : "r"(_m), "r"(_p) : "memory");                                \
    if (!_d) {                                                                    \
        asm volatile("{ .reg .pred P1; WL_%=: mbarrier.try_wait.parity.acquire.cta.shared::cta.b64 P1, [%0], %1, 0x989680; @P1 bra.uni WD_%=; bra.uni WL_%=; WD_%=: }" \
            :: "r"(_m), "r"(_p) : "memory");                                      \
    }                                                                             \
} while (0)

__device__ __forceinline__ void tma2d(uint32_t dst, const CUtensorMap* m,
                                      int cx, int cy, uint32_t mbar) {
    asm volatile(
        "cp.async.bulk.tensor.2d.shared::cta.global.tile.mbarrier::complete_tx::bytes "
        "[%0], [%1, {%2, %3}], [%4];"
        :: "r"(dst), "l"(m), "r"(cx), "r"(cy), "r"(mbar) : "memory");
}

#define FENCE_PROXY_ASYNC() asm volatile("fence.proxy.async.shared::cta;" ::: "memory")

__device__ __forceinline__ void ldsm4(uint32_t* r, uint32_t addr) {
    asm volatile("ldmatrix.sync.aligned.m8n8.x4.shared.b16 {%0,%1,%2,%3}, [%4];"
                 : "=r"(r[0]), "=r"(r[1]), "=r"(r[2]), "=r"(r[3]) : "r"(addr));
}

__device__ __forceinline__ void mma16816(float* c, const uint32_t* a, uint32_t b0, uint32_t b1) {
    asm volatile(
        "mma.sync.aligned.m16n8k16.row.col.f32.bf16.bf16.f32 "
        "{%0,%1,%2,%3}, {%4,%5,%6,%7}, {%8,%9}, {%0,%1,%2,%3};"
        : "+f"(c[0]), "+f"(c[1]), "+f"(c[2]), "+f"(c[3])
        : "r"(a[0]), "r"(a[1]), "r"(a[2]), "r"(a[3]), "r"(b0), "r"(b1));
}

// ---------------- split conversion --------------
__global__ void split_fp32(const float* __restrict__ src,
                           __nv_bfloat16* __restrict__ hi,
                           __nv_bfloat16* __restrict__ lo, size_t n4)
{
    size_t i = (size_t)blockIdx.x * blockDim.x + threadIdx.x;
    if (i >= n4) return;
    float4 v = reinterpret_cast<const float4*>(src)[i];
    __nv_bfloat16 h0 = __float2bfloat16_rn(v.x);
    __nv_bfloat16 h1 = __float2bfloat16_rn(v.y);
    __nv_bfloat16 h2 = __float2bfloat16_rn(v.z);
    __nv_bfloat16 h3 = __float2bfloat16_rn(v.w);
    __nv_bfloat16 l0 = __float2bfloat16_rn(v.x - __bfloat162float(h0));
    __nv_bfloat16 l1 = __float2bfloat16_rn(v.y - __bfloat162float(h1));
    __nv_bfloat16 l2 = __float2bfloat16_rn(v.z - __bfloat162float(h2));
    __nv_bfloat16 l3 = __float2bfloat16_rn(v.w - __bfloat162float(h3));
    uint2 ph, pl;
    ph.x = (uint32_t)__bfloat16_as_ushort(h0) | ((uint32_t)__bfloat16_as_ushort(h1) << 16);
    ph.y = (uint32_t)__bfloat16_as_ushort(h2) | ((uint32_t)__bfloat16_as_ushort(h3) << 16);
    pl.x = (uint32_t)__bfloat16_as_ushort(l0) | ((uint32_t)__bfloat16_as_ushort(l1) << 16);
    pl.y = (uint32_t)__bfloat16_as_ushort(l2) | ((uint32_t)__bfloat16_as_ushort(l3) << 16);
    reinterpret_cast<uint2*>(hi)[i] = ph;
    reinterpret_cast<uint2*>(lo)[i] = pl;
}

// ---------------- HMMA GEMM ---------------------
// D[BM,BN] += (Ah+Al) @ (Bh+Bl)^T  (3-term bf16 split), K streamed by TMA.
// MODE 0: relu(acc + bias) -> split bf16 into g_h1h/g_h1l
// MODE 1: acc + bias -> fp32 outp (cols guarded to ONN_)
template <int MODE>
__global__ __launch_bounds__(256, 1)
void gemm_hmma(const __grid_constant__ CUtensorMap a0h,
               const __grid_constant__ CUtensorMap a0l,
               const __grid_constant__ CUtensorMap a1h,
               const __grid_constant__ CUtensorMap a1l,
               const __grid_constant__ CUtensorMap bh,
               const __grid_constant__ CUtensorMap bl,
               int K0, int K1, int bk1,
               const float* __restrict__ bias,
               float* __restrict__ outp)
{
    extern __shared__ __align__(1024) char smem[];
    const uint32_t sbase = smem_u32(smem);
    const uint32_t FULLB[2]  = { sbase + 0,  sbase + 8  };
    const uint32_t EMPTYB[2] = { sbase + 16, sbase + 24 };

    const int tid  = threadIdx.x;
    const int lane = tid & 31;
    const int wid  = tid >> 5;
    const int wm   = (wid & 1) * 64;    // warp M offset in tile
    const int wn   = (wid >> 1) * 32;   // warp N offset in tile

    if (tid == 0) {
        MBARRIER_INIT(FULLB[0], 1);
        MBARRIER_INIT(FULLB[1], 1);
        MBARRIER_INIT(EMPTYB[0], 256);
        MBARRIER_INIT(EMPTYB[1], 256);
        FENCE_PROXY_ASYNC();
    }
    __syncthreads();

    const int m0 = blockIdx.x * BM;
    const int n0 = blockIdx.y * BN;
    const int S0 = K0 / KC;
    const int T  = (K0 + K1) / KC;

    // per-lane ldmatrix addressing pieces (SW128 swizzle: chunk ^= row&7)
    const uint32_t rowoff = (uint32_t)(lane & 15) * 128u;
    const uint32_t hi4 = (uint32_t)(lane >> 4);
    const uint32_t lo7 = (uint32_t)(lane & 7);
    uint32_t cb[4];
    #pragma unroll
    for (int ks = 0; ks < 4; ks++)
        cb[ks] = (((2u * ks + hi4) ^ lo7) << 4);

    float acc[4][4][4];
    #pragma unroll
    for (int mi = 0; mi < 4; mi++)
        #pragma unroll
        for (int ni = 0; ni < 4; ni++)
            #pragma unroll
            for (int q = 0; q < 4; q++) acc[mi][ni][q] = 0.f;

    // prologue: producer fills both stages
    if (tid == 0) {
        #pragma unroll
        for (int j = 0; j < 2; j++) {
            const uint32_t full = FULLB[j];
            MBARRIER_EXPECT_TX(full, STAGE_BYTES);
            const uint32_t sb = sbase + STAGE0_OFF + (uint32_t)j * STAGE_SZ;
            const CUtensorMap *mah, *mal; int ak, bk;
            if (j < S0) { mah = &a0h; mal = &a0l; ak = j * KC; bk = j * KC; }
            else        { mah = &a1h; mal = &a1l; ak = (j - S0) * KC; bk = bk1 + (j - S0) * KC; }
            tma2d(sb + STG_AH, mah, ak, m0, full);
            tma2d(sb + STG_AL, mal, ak, m0, full);
            tma2d(sb + STG_BH, &bh, bk, n0, full);
            tma2d(sb + STG_BL, &bl, bk, n0, full);
        }
    }

    for (int i = 0; i < T; i++) {
        const int s = i & 1;
        const uint32_t ph = (uint32_t)((i >> 1) & 1);
        MBARRIER_WAIT_PARITY(FULLB[s], ph);

        const uint32_t sb  = sbase + STAGE0_OFF + (uint32_t)s * STAGE_SZ;
        const uint32_t aHb = sb + STG_AH + (uint32_t)wm * 128u + rowoff;
        const uint32_t aLb = sb + STG_AL + (uint32_t)wm * 128u + rowoff;
        const uint32_t bHb = sb + STG_BH + (uint32_t)wn * 128u + rowoff;
        const uint32_t bLb = sb + STG_BL + (uint32_t)wn * 128u + rowoff;

        #pragma unroll
        for (int ks = 0; ks < 4; ks++) {
            uint32_t ah[4][4], al[4][4], bb[2][4];
            #pragma unroll
            for (int mi = 0; mi < 4; mi++)
                ldsm4(ah[mi], aHb + (uint32_t)mi * (16u * 128u) + cb[ks]);
            #pragma unroll
            for (int mi = 0; mi < 4; mi++)
                ldsm4(al[mi], aLb + (uint32_t)mi * (16u * 128u) + cb[ks]);
            #pragma unroll
            for (int nj = 0; nj < 2; nj++)
                ldsm4(bb[nj], bHb + (uint32_t)nj * (16u * 128u) + cb[ks]);

            // Ah*Bh and Al*Bh
            #pragma unroll
            for (int mi = 0; mi < 4; mi++)
                #pragma unroll
                for (int ni = 0; ni < 4; ni++) {
                    const uint32_t b0 = bb[ni >> 1][ni & 1];
                    const uint32_t b1 = bb[ni >> 1][(ni & 1) + 2];
                    mma16816(acc[mi][ni], ah[mi], b0, b1);
                }
            #pragma unroll
            for (int mi = 0; mi < 4; mi++)
                #pragma unroll
                for (int ni = 0; ni < 4; ni++) {
                    const uint32_t b0 = bb[ni >> 1][ni & 1];
                    const uint32_t b1 = bb[ni >> 1][(ni & 1) + 2];
                    mma16816(acc[mi][ni], al[mi], b0, b1);
                }
            // Ah*Bl
            #pragma unroll
            for (int nj = 0; nj < 2; nj++)
                ldsm4(bb[nj], bLb + (uint32_t)nj * (16u * 128u) + cb[ks]);
            #pragma unroll
            for (int mi = 0; mi < 4; mi++)
                #pragma unroll
                for (int ni = 0; ni < 4; ni++) {
                    const uint32_t b0 = bb[ni >> 1][ni & 1];
                    const uint32_t b1 = bb[ni >> 1][(ni & 1) + 2];
                    mma16816(acc[mi][ni], ah[mi], b0, b1);
                }
        }

        MBARRIER_ARRIVE(EMPTYB[s]);

        // producer refill
        const int j = i + 2;
        if (tid == 0 && j < T) {
            MBARRIER_WAIT_PARITY(EMPTYB[s], ph);
            const uint32_t full = FULLB[s];
            MBARRIER_EXPECT_TX(full, STAGE_BYTES);
            const CUtensorMap *mah, *mal; int ak, bk;
            if (j < S0) { mah = &a0h; mal = &a0l; ak = j * KC; bk = j * KC; }
            else        { mah = &a1h; mal = &a1l; ak = (j - S0) * KC; bk = bk1 + (j - S0) * KC; }
            tma2d(sb + STG_AH, mah, ak, m0, full);
            tma2d(sb + STG_AL, mal, ak, m0, full);
            tma2d(sb + STG_BH, &bh, bk, n0, full);
            tma2d(sb + STG_BL, &bl, bk, n0, full);
        }
    }

    // ---------------- epilogue ----------------
    const int mrow = m0 + wm + (lane >> 2);
    const int ncol = n0 + wn + 2 * (lane & 3);

    #pragma unroll
    for (int mi = 0; mi < 4; mi++) {
        #pragma unroll
        for (int ni = 0; ni < 4; ni++) {
            const int n = ncol + ni * 8;
            const int ma = mrow + mi * 16;
            const int mb = ma + 8;
            if (MODE == 1 && n >= ONN_) continue;
            const float2 bv = __ldg(reinterpret_cast<const float2*>(bias + n));
            float v00 = acc[mi][ni][0] + bv.x;
            float v01 = acc[mi][ni][1] + bv.y;
            float v10 = acc[mi][ni][2] + bv.x;
            float v11 = acc[mi][ni][3] + bv.y;
            if (MODE == 0) {
                v00 = v00 > 0.f ? v00 : 0.f;
                v01 = v01 > 0.f ? v01 : 0.f;
                v10 = v10 > 0.f ? v10 : 0.f;
                v11 = v11 > 0.f ? v11 : 0.f;
                __nv_bfloat16 h00 = __float2bfloat16_rn(v00);
                __nv_bfloat16 h01 = __float2bfloat16_rn(v01);
                __nv_bfloat16 h10 = __float2bfloat16_rn(v10);
                __nv_bfloat16 h11 = __float2bfloat16_rn(v11);
                __nv_bfloat16 l00 = __float2bfloat16_rn(v00 - __bfloat162float(h00));
                __nv_bfloat16 l01 = __float2bfloat16_rn(v01 - __bfloat162float(h01));
                __nv_bfloat16 l10 = __float2bfloat16_rn(v10 - __bfloat162float(h10));
                __nv_bfloat16 l11 = __float2bfloat16_rn(v11 - __bfloat162float(h11));
                uint32_t ph0 = (uint32_t)__bfloat16_as_ushort(h00) | ((uint32_t)__bfloat16_as_ushort(h01) << 16);
                uint32_t ph1 = (uint32_t)__bfloat16_as_ushort(h10) | ((uint32_t)__bfloat16_as_ushort(h11) << 16);
                uint32_t pl0 = (uint32_t)__bfloat16_as_ushort(l00) | ((uint32_t)__bfloat16_as_ushort(l01) << 16);
                uint32_t pl1 = (uint32_t)__bfloat16_as_ushort(l10) | ((uint32_t)__bfloat16_as_ushort(l11) << 16);
                *reinterpret_cast<uint32_t*>(g_h1h + (size_t)ma * HID_ + n) = ph0;
                *reinterpret_cast<uint32_t*>(g_h1h + (size_t)mb * HID_ + n) = ph1;
                *reinterpret_cast<uint32_t*>(g_h1l + (size_t)ma * HID_ + n) = pl0;
                *reinterpret_cast<uint32_t*>(g_h1l + (size_t)mb * HID_ + n) = pl1;
            } else {
                float2 o0 = { v00, v01 };
                float2 o1 = { v10, v11 };
                *reinterpret_cast<float2*>(outp + (size_t)ma * ONN_ + n) = o0;
                *reinterpret_cast<float2*>(outp + (size_t)mb * ONN_ + n) = o1;
            }
        }
    }
}

// ---------------- host side ---------------------
typedef CUresult (*PFN_tmap)(CUtensorMap*, CUtensorMapDataType, cuuint32_t, void*,
                             const cuuint64_t*, const cuuint64_t*, const cuuint32_t*,
                             const cuuint32_t*, CUtensorMapInterleave, CUtensorMapSwizzle,
                             CUtensorMapL2promotion, CUtensorMapFloatOOBfill);

static void mk2d(PFN_tmap f, CUtensorMap* m, void* p,
                 unsigned long long k, unsigned long long rows, unsigned box1)
{
    cuuint64_t dims[2] = { k, rows };
    cuuint64_t str[1]  = { k * 2 };        // row stride in bytes (bf16)
    cuuint32_t box[2]  = { 64u, box1 };
    cuuint32_t es[2]   = { 1u, 1u };
    f(m, CU_TENSOR_MAP_DATA_TYPE_BFLOAT16, 2, p, dims, str, box, es,
      CU_TENSOR_MAP_INTERLEAVE_NONE, CU_TENSOR_MAP_SWIZZLE_128B,
      CU_TENSOR_MAP_L2_PROMOTION_L2_128B, CU_TENSOR_MAP_FLOAT_OOB_FILL_NONE);
}

extern "C" void kernel_launch(void* const* d_in, const int* in_sizes, int n_in,
                              void* d_out, int out_size)
{
    const float* x  = (const float*)d_in[0];
    const float* W1 = (const float*)d_in[1];
    const float* b1 = (const float*)d_in[2];
    const float* W2 = (const float*)d_in[3];
    const float* b2 = (const float*)d_in[4];
    float* out = (float*)d_out;

    void *xh, *xl, *w1h, *w1l, *w2h, *w2l, *h1h, *h1l;
    cudaGetSymbolAddress(&xh,  g_xh);  cudaGetSymbolAddress(&xl,  g_xl);
    cudaGetSymbolAddress(&w1h, g_w1h); cudaGetSymbolAddress(&w1l, g_w1l);
    cudaGetSymbolAddress(&w2h, g_w2h); cudaGetSymbolAddress(&w2l, g_w2l);
    cudaGetSymbolAddress(&h1h, g_h1h); cudaGetSymbolAddress(&h1l, g_h1l);

    // conversions (fp32 -> bf16 hi/lo)
    {
        size_t n4x  = (size_t)MB_ * DIN_ / 4;
        size_t n4w1 = (size_t)HID_ * DIN_ / 4;
        size_t n4w2 = (size_t)ONN_ * K2_ / 4;
        split_fp32<<<(unsigned)((n4x  + 255) / 256), 256>>>(x,  (__nv_bfloat16*)xh,  (__nv_bfloat16*)xl,  n4x);
        split_fp32<<<(unsigned)((n4w1 + 255) / 256), 256>>>(W1, (__nv_bfloat16*)w1h, (__nv_bfloat16*)w1l, n4w1);
        split_fp32<<<(unsigned)((n4w2 + 255) / 256), 256>>>(W2, (__nv_bfloat16*)w2h, (__nv_bfloat16*)w2l, n4w2);
    }

    // tensor maps via driver entry point (no -lcuda link needed)
    PFN_tmap enc = nullptr;
    cudaDriverEntryPointQueryResult qr;
    cudaGetDriverEntryPoint("cuTensorMapEncodeTiled", (void**)&enc,
                            cudaEnableDefault, &qr);

    CUtensorMap m_xh, m_xl, m_w1h, m_w1l, m_h1h, m_h1l, m_w2h, m_w2l;
    mk2d(enc, &m_xh,  xh,  DIN_, MB_,  BM);    // A maps (box1 = BM)
    mk2d(enc, &m_xl,  xl,  DIN_, MB_,  BM);
    mk2d(enc, &m_h1h, h1h, HID_, MB_,  BM);
    mk2d(enc, &m_h1l, h1l, HID_, MB_,  BM);
    mk2d(enc, &m_w1h, w1h, DIN_, HID_, BN);    // B maps (box1 = BN)
    mk2d(enc, &m_w1l, w1l, DIN_, HID_, BN);
    mk2d(enc, &m_w2h, w2h, K2_,  ONN_, BN);
    mk2d(enc, &m_w2l, w2l, K2_,  ONN_, BN);

    cudaFuncSetAttribute(gemm_hmma<0>, cudaFuncAttributeMaxDynamicSharedMemorySize, SMEM_TOTAL);
    cudaFuncSetAttribute(gemm_hmma<1>, cudaFuncAttributeMaxDynamicSharedMemorySize, SMEM_TOTAL);

    // GEMM1: h1 = relu(x @ W1^T + b1); M-fastest grid for W1-band L2 reuse
    dim3 g1(MB_ / BM, HID_ / BN);   // (32, 128)
    gemm_hmma<0><<<g1, 256, SMEM_TOTAL>>>(m_xh, m_xl, m_xh, m_xl, m_w1h, m_w1l,
                                          DIN_, 0, 0, b1, nullptr);

    // GEMM2: out = [x, h1] @ W2^T + b2
    dim3 g2(MB_ / BM, (ONN_ + BN - 1) / BN);   // (32, 8)
    gemm_hmma<1><<<g2, 256, SMEM_TOTAL>>>(m_xh, m_xl, m_h1h, m_h1l, m_w2h, m_w2l,
                                          DIN_, HID_, DIN_, b2, out);
}

// round 4
// speedup vs baseline: 2.9532x; 1.0204x over previous
#include <cuda_runtime.h>
#include <cuda_bf16.h>
#include <cuda.h>
#include <cstdint>
#include <cstddef>

// ---------------- problem dims ----------------
#define MB_   4096
#define DIN_  4096
#define HID_  16384
#define ONN_  1000
#define K2_   (DIN_ + HID_)

#define KC 64                   // bf16 K per stage (128 B rows = SW128 atom)
#define NSTAGE 3
#define STAGE0_OFF 1024

// bf16 split scratch (static device arrays — no allocation)
__device__ __align__(1024) __nv_bfloat16 g_xh [(size_t)MB_ * DIN_];
__device__ __align__(1024) __nv_bfloat16 g_xl [(size_t)MB_ * DIN_];
__device__ __align__(1024) __nv_bfloat16 g_w1h[(size_t)HID_ * DIN_];
__device__ __align__(1024) __nv_bfloat16 g_w1l[(size_t)HID_ * DIN_];
__device__ __align__(1024) __nv_bfloat16 g_w2h[(size_t)ONN_ * K2_];
__device__ __align__(1024) __nv_bfloat16 g_w2l[(size_t)ONN_ * K2_];
__device__ __align__(1024) __nv_bfloat16 g_h1h[(size_t)MB_ * HID_];
__device__ __align__(1024) __nv_bfloat16 g_h1l[(size_t)MB_ * HID_];

// ---------------- PTX helpers ------------------
__device__ __forceinline__ uint32_t smem_u32(const void* p) {
    uint32_t a;
    asm("{ .reg .u64 t; cvta.to.shared.u64 t, %1; cvt.u32.u64 %0, t; }"
        : "=r"(a) : "l"(p));
    return a;
}

#define MBARRIER_INIT(addr, cnt) \
    asm volatile("mbarrier.init.shared.b64 [%0], %1;" :: "r"(addr), "r"(cnt) : "memory")

#define MBARRIER_EXPECT_TX(addr, bytes) \
    asm volatile("mbarrier.arrive.expect_tx.shared.b64 _, [%0], %1;" \
                 :: "r"(addr), "r"(bytes) : "memory")

#define MBARRIER_ARRIVE(addr) \
    asm volatile("mbarrier.arrive.shared.b64 _, [%0];" :: "r"(addr) : "memory")

#define MBARRIER_WAIT_PARITY(addr, parity) do {                                   \
    uint32_t _m = (addr); uint32_t _p = (parity); uint32_t _d;                    \
    asm volatile("{ .reg .pred p; mbarrier.try_wait.parity.acquire.cta.shared::cta.b64 p, [%1], %2; selp.b32 %0, 1, 0, p; }" \
        : "=r"(_d) : "r"(_m), "r"(_p) : "memory");                                \
    if (!_d) {                                                                    \
        asm volatile("{ .reg .pred P1; WL_%=: mbarrier.try_wait.parity.acquire.cta.shared::cta.b64 P1, [%0], %1, 0x989680; @P1 bra.uni WD_%=; bra.uni WL_%=; WD_%=: }" \
            :: "r"(_m), "r"(_p) : "memory");                                      \
    }                                                                             \
} while (0)

__device__ __forceinline__ void tma2d(uint32_t dst, const CUtensorMap* m,
                                      int cx, int cy, uint32_t mbar) {
    asm volatile(
        "cp.async.bulk.tensor.2d.shared::cta.global.tile.mbarrier::complete_tx::bytes "
        "[%0], [%1, {%2, %3}], [%4];"
        :: "r"(dst), "l"(m), "r"(cx), "r"(cy), "r"(mbar) : "memory");
}

#define FENCE_PROXY_ASYNC() asm volatile("fence.proxy.async.shared::cta;" ::: "memory")

__device__ __forceinline__ void ldsm4(uint32_t* r, uint32_t addr) {
    asm volatile("ldmatrix.sync.aligned.m8n8.x4.shared.b16 {%0,%1,%2,%3}, [%4];"
                 : "=r"(r[0]), "=r"(r[1]), "=r"(r[2]), "=r"(r[3]) : "r"(addr));
}

__device__ __forceinline__ void mma16816(float* c, const uint32_t* a, uint32_t b0, uint32_t b1) {
    asm volatile(
        "mma.sync.aligned.m16n8k16.row.col.f32.bf16.bf16.f32 "
        "{%0,%1,%2,%3}, {%4,%5,%6,%7}, {%8,%9}, {%0,%1,%2,%3};"
        : "+f"(c[0]), "+f"(c[1]), "+f"(c[2]), "+f"(c[3])
        : "r"(a[0]), "r"(a[1]), "r"(a[2]), "r"(a[3]), "r"(b0), "r"(b1));
}

// ---------------- split conversion --------------
__global__ void split_fp32(const float* __restrict__ src,
                           __nv_bfloat16* __restrict__ hi,
                           __nv_bfloat16* __restrict__ lo, size_t n4)
{
    size_t i = (size_t)blockIdx.x * blockDim.x + threadIdx.x;
    if (i >= n4) return;
    float4 v = reinterpret_cast<const float4*>(src)[i];
    __nv_bfloat16 h0 = __float2bfloat16_rn(v.x);
    __nv_bfloat16 h1 = __float2bfloat16_rn(v.y);
    __nv_bfloat16 h2 = __float2bfloat16_rn(v.z);
    __nv_bfloat16 h3 = __float2bfloat16_rn(v.w);
    __nv_bfloat16 l0 = __float2bfloat16_rn(v.x - __bfloat162float(h0));
    __nv_bfloat16 l1 = __float2bfloat16_rn(v.y - __bfloat162float(h1));
    __nv_bfloat16 l2 = __float2bfloat16_rn(v.z - __bfloat162float(h2));
    __nv_bfloat16 l3 = __float2bfloat16_rn(v.w - __bfloat162float(h3));
    uint2 ph, pl;
    ph.x = (uint32_t)__bfloat16_as_ushort(h0) | ((uint32_t)__bfloat16_as_ushort(h1) << 16);
    ph.y = (uint32_t)__bfloat16_as_ushort(h2) | ((uint32_t)__bfloat16_as_ushort(h3) << 16);
    pl.x = (uint32_t)__bfloat16_as_ushort(l0) | ((uint32_t)__bfloat16_as_ushort(l1) << 16);
    pl.y = (uint32_t)__bfloat16_as_ushort(l2) | ((uint32_t)__bfloat16_as_ushort(l3) << 16);
    reinterpret_cast<uint2*>(hi)[i] = ph;
    reinterpret_cast<uint2*>(lo)[i] = pl;
}

// ---------------- HMMA GEMM ---------------------
// D[TBM,128] += (Ah+Al) @ (Bh+Bl)^T  (3-term bf16 split), K streamed by TMA.
// MODE 0: relu(acc + bias) -> split bf16 into g_h1h/g_h1l
// MODE 1: acc + bias -> fp32 outp (cols guarded to ONN_)
// Warp grid fixed 2(M) x 4(N); warp tile = (TBM/2) x 32.
template <int MODE, int TBM>
__global__ __launch_bounds__(256, 1)
void gemm_hmma(const __grid_constant__ CUtensorMap a0h,
               const __grid_constant__ CUtensorMap a0l,
               const __grid_constant__ CUtensorMap a1h,
               const __grid_constant__ CUtensorMap a1l,
               const __grid_constant__ CUtensorMap bh,
               const __grid_constant__ CUtensorMap bl,
               int K0, int K1, int bk1,
               const float* __restrict__ bias,
               float* __restrict__ outp)
{
    constexpr int MI = TBM / 32;                      // 16-row A fragments per warp
    constexpr uint32_t ASZ = (uint32_t)TBM * 128u;    // bytes of one A operand / stage
    constexpr uint32_t STG_AH = 0;
    constexpr uint32_t STG_AL = ASZ;
    constexpr uint32_t STG_BH = 2u * ASZ;
    constexpr uint32_t STG_BL = 2u * ASZ + 16384u;
    constexpr uint32_t STAGE_SZ = 2u * ASZ + 32768u;
    constexpr uint32_t STAGE_BYTES = STAGE_SZ;

    extern __shared__ __align__(1024) char smem[];
    const uint32_t sbase = smem_u32(smem);

    const int tid  = threadIdx.x;
    const int lane = tid & 31;
    const int wid  = tid >> 5;
    const int wm   = (wid & 1) * (TBM / 2);
    const int wn   = (wid >> 1) * 32;

    if (tid == 0) {
        #pragma unroll
        for (int s = 0; s < NSTAGE; s++) {
            MBARRIER_INIT(sbase + 8u * s, 1);            // FULL[s]
            MBARRIER_INIT(sbase + 64u + 8u * s, 8);      // EMPTY[s], per-warp arrival
        }
        FENCE_PROXY_ASYNC();
    }
    __syncthreads();

    const int m0 = blockIdx.x * TBM;
    const int n0 = blockIdx.y * 128;
    const int S0 = K0 / KC;
    const int T  = (K0 + K1) / KC;

    // per-lane ldmatrix addressing pieces (SW128 swizzle: chunk ^= row&7)
    const uint32_t rowoff = (uint32_t)(lane & 15) * 128u;
    const uint32_t hi4 = (uint32_t)(lane >> 4);
    const uint32_t lo7 = (uint32_t)(lane & 7);
    uint32_t cb[4];
    #pragma unroll
    for (int ks = 0; ks < 4; ks++)
        cb[ks] = (((2u * ks + hi4) ^ lo7) << 4);

    float acc[MI][4][4];
    #pragma unroll
    for (int mi = 0; mi < MI; mi++)
        #pragma unroll
        for (int ni = 0; ni < 4; ni++)
            #pragma unroll
            for (int q = 0; q < 4; q++) acc[mi][ni][q] = 0.f;

    // prologue: producer fills all stages
    if (tid == 0) {
        #pragma unroll
        for (int j = 0; j < NSTAGE; j++) {
            const uint32_t full = sbase + 8u * j;
            MBARRIER_EXPECT_TX(full, STAGE_BYTES);
            const uint32_t sb = sbase + STAGE0_OFF + (uint32_t)j * STAGE_SZ;
            const CUtensorMap *mah, *mal; int ak, bk;
            if (j < S0) { mah = &a0h; mal = &a0l; ak = j * KC; bk = j * KC; }
            else        { mah = &a1h; mal = &a1l; ak = (j - S0) * KC; bk = bk1 + (j - S0) * KC; }
            tma2d(sb + STG_AH, mah, ak, m0, full);
            tma2d(sb + STG_AL, mal, ak, m0, full);
            tma2d(sb + STG_BH, &bh, bk, n0, full);
            tma2d(sb + STG_BL, &bl, bk, n0, full);
        }
    }

    int s = 0, ph = 0;
    #pragma unroll 1
    for (int i = 0; i < T; i++) {
        MBARRIER_WAIT_PARITY(sbase + 8u * s, (uint32_t)ph);

        const uint32_t sb  = sbase + STAGE0_OFF + (uint32_t)s * STAGE_SZ;
        const uint32_t aHb = sb + STG_AH + (uint32_t)wm * 128u + rowoff;
        const uint32_t aLb = sb + STG_AL + (uint32_t)wm * 128u + rowoff;
        const uint32_t bHb = sb + STG_BH + (uint32_t)wn * 128u + rowoff;
        const uint32_t bLb = sb + STG_BL + (uint32_t)wn * 128u + rowoff;

        #pragma unroll
        for (int ks = 0; ks < 4; ks++) {
            uint32_t ah[MI][4], al[MI][4], bb[2][4];
            #pragma unroll
            for (int mi = 0; mi < MI; mi++)
                ldsm4(ah[mi], aHb + (uint32_t)mi * (16u * 128u) + cb[ks]);
            #pragma unroll
            for (int mi = 0; mi < MI; mi++)
                ldsm4(al[mi], aLb + (uint32_t)mi * (16u * 128u) + cb[ks]);
            #pragma unroll
            for (int nj = 0; nj < 2; nj++)
                ldsm4(bb[nj], bHb + (uint32_t)nj * (16u * 128u) + cb[ks]);

            #pragma unroll
            for (int mi = 0; mi < MI; mi++)
                #pragma unroll
                for (int ni = 0; ni < 4; ni++) {
                    const uint32_t b0 = bb[ni >> 1][ni & 1];
                    const uint32_t b1 = bb[ni >> 1][(ni & 1) + 2];
                    mma16816(acc[mi][ni], ah[mi], b0, b1);
                }
            #pragma unroll
            for (int mi = 0; mi < MI; mi++)
                #pragma unroll
                for (int ni = 0; ni < 4; ni++) {
                    const uint32_t b0 = bb[ni >> 1][ni & 1];
                    const uint32_t b1 = bb[ni >> 1][(ni & 1) + 2];
                    mma16816(acc[mi][ni], al[mi], b0, b1);
                }
            #pragma unroll
            for (int nj = 0; nj < 2; nj++)
                ldsm4(bb[nj], bLb + (uint32_t)nj * (16u * 128u) + cb[ks]);
            #pragma unroll
            for (int mi = 0; mi < MI; mi++)
                #pragma unroll
                for (int ni = 0; ni < 4; ni++) {
                    const uint32_t b0 = bb[ni >> 1][ni & 1];
                    const uint32_t b1 = bb[ni >> 1][(ni & 1) + 2];
                    mma16816(acc[mi][ni], ah[mi], b0, b1);
                }
        }

        if (lane == 0) MBARRIER_ARRIVE(sbase + 64u + 8u * s);

        // producer refill
        const int j = i + NSTAGE;
        if (tid == 0 && j < T) {
            MBARRIER_WAIT_PARITY(sbase + 64u + 8u * s, (uint32_t)ph);
            const uint32_t full = sbase + 8u * s;
            MBARRIER_EXPECT_TX(full, STAGE_BYTES);
            const CUtensorMap *mah, *mal; int ak, bk;
            if (j < S0) { mah = &a0h; mal = &a0l; ak = j * KC; bk = j * KC; }
            else        { mah = &a1h; mal = &a1l; ak = (j - S0) * KC; bk = bk1 + (j - S0) * KC; }
            tma2d(sb + STG_AH, mah, ak, m0, full);
            tma2d(sb + STG_AL, mal, ak, m0, full);
            tma2d(sb + STG_BH, &bh, bk, n0, full);
            tma2d(sb + STG_BL, &bl, bk, n0, full);
        }
        if (++s == NSTAGE) { s = 0; ph ^= 1; }
    }

    // ---------------- epilogue ----------------
    const int mrow = m0 + wm + (lane >> 2);
    const int ncol = n0 + wn + 2 * (lane & 3);

    #pragma unroll
    for (int mi = 0; mi < MI; mi++) {
        #pragma unroll
        for (int ni = 0; ni < 4; ni++) {
            const int n = ncol + ni * 8;
            const int ma = mrow + mi * 16;
            const int mb = ma + 8;
            if (MODE == 1 && n >= ONN_) continue;
            const float2 bv = __ldg(reinterpret_cast<const float2*>(bias + n));
            float v00 = acc[mi][ni][0] + bv.x;
            float v01 = acc[mi][ni][1] + bv.y;
            float v10 = acc[mi][ni][2] + bv.x;
            float v11 = acc[mi][ni][3] + bv.y;
            if (MODE == 0) {
                v00 = v00 > 0.f ? v00 : 0.f;
                v01 = v01 > 0.f ? v01 : 0.f;
                v10 = v10 > 0.f ? v10 : 0.f;
                v11 = v11 > 0.f ? v11 : 0.f;
                __nv_bfloat16 h00 = __float2bfloat16_rn(v00);
                __nv_bfloat16 h01 = __float2bfloat16_rn(v01);
                __nv_bfloat16 h10 = __float2bfloat16_rn(v10);
                __nv_bfloat16 h11 = __float2bfloat16_rn(v11);
                __nv_bfloat16 l00 = __float2bfloat16_rn(v00 - __bfloat162float(h00));
                __nv_bfloat16 l01 = __float2bfloat16_rn(v01 - __bfloat162float(h01));
                __nv_bfloat16 l10 = __float2bfloat16_rn(v10 - __bfloat162float(h10));
                __nv_bfloat16 l11 = __float2bfloat16_rn(v11 - __bfloat162float(h11));
                uint32_t ph0 = (uint32_t)__bfloat16_as_ushort(h00) | ((uint32_t)__bfloat16_as_ushort(h01) << 16);
                uint32_t ph1 = (uint32_t)__bfloat16_as_ushort(h10) | ((uint32_t)__bfloat16_as_ushort(h11) << 16);
                uint32_t pl0 = (uint32_t)__bfloat16_as_ushort(l00) | ((uint32_t)__bfloat16_as_ushort(l01) << 16);
                uint32_t pl1 = (uint32_t)__bfloat16_as_ushort(l10) | ((uint32_t)__bfloat16_as_ushort(l11) << 16);
                *reinterpret_cast<uint32_t*>(g_h1h + (size_t)ma * HID_ + n) = ph0;
                *reinterpret_cast<uint32_t*>(g_h1h + (size_t)mb * HID_ + n) = ph1;
                *reinterpret_cast<uint32_t*>(g_h1l + (size_t)ma * HID_ + n) = pl0;
                *reinterpret_cast<uint32_t*>(g_h1l + (size_t)mb * HID_ + n) = pl1;
            } else {
                float2 o0 = { v00, v01 };
                float2 o1 = { v10, v11 };
                *reinterpret_cast<float2*>(outp + (size_t)ma * ONN_ + n) = o0;
                *reinterpret_cast<float2*>(outp + (size_t)mb * ONN_ + n) = o1;
            }
        }
    }
}

// ---------------- host side ---------------------
typedef CUresult (*PFN_tmap)(CUtensorMap*, CUtensorMapDataType, cuuint32_t, void*,
                             const cuuint64_t*, const cuuint64_t*, const cuuint32_t*,
                             const cuuint32_t*, CUtensorMapInterleave, CUtensorMapSwizzle,
                             CUtensorMapL2promotion, CUtensorMapFloatOOBfill);

static void mk2d(PFN_tmap f, CUtensorMap* m, void* p,
                 unsigned long long k, unsigned long long rows, unsigned box1)
{
    cuuint64_t dims[2] = { k, rows };
    cuuint64_t str[1]  = { k * 2 };        // row stride in bytes (bf16)
    cuuint32_t box[2]  = { 64u, box1 };
    cuuint32_t es[2]   = { 1u, 1u };
    f(m, CU_TENSOR_MAP_DATA_TYPE_BFLOAT16, 2, p, dims, str, box, es,
      CU_TENSOR_MAP_INTERLEAVE_NONE, CU_TENSOR_MAP_SWIZZLE_128B,
      CU_TENSOR_MAP_L2_PROMOTION_L2_128B, CU_TENSOR_MAP_FLOAT_OOB_FILL_NONE);
}

extern "C" void kernel_launch(void* const* d_in, const int* in_sizes, int n_in,
                              void* d_out, int out_size)
{
    const float* x  = (const float*)d_in[0];
    const float* W1 = (const float*)d_in[1];
    const float* b1 = (const float*)d_in[2];
    const float* W2 = (const float*)d_in[3];
    const float* b2 = (const float*)d_in[4];
    float* out = (float*)d_out;

    void *xh, *xl, *w1h, *w1l, *w2h, *w2l, *h1h, *h1l;
    cudaGetSymbolAddress(&xh,  g_xh);  cudaGetSymbolAddress(&xl,  g_xl);
    cudaGetSymbolAddress(&w1h, g_w1h); cudaGetSymbolAddress(&w1l, g_w1l);
    cudaGetSymbolAddress(&w2h, g_w2h); cudaGetSymbolAddress(&w2l, g_w2l);
    cudaGetSymbolAddress(&h1h, g_h1h); cudaGetSymbolAddress(&h1l, g_h1l);

    // conversions (fp32 -> bf16 hi/lo)
    {
        size_t n4x  = (size_t)MB_ * DIN_ / 4;
        size_t n4w1 = (size_t)HID_ * DIN_ / 4;
        size_t n4w2 = (size_t)ONN_ * K2_ / 4;
        split_fp32<<<(unsigned)((n4x  + 255) / 256), 256>>>(x,  (__nv_bfloat16*)xh,  (__nv_bfloat16*)xl,  n4x);
        split_fp32<<<(unsigned)((n4w1 + 255) / 256), 256>>>(W1, (__nv_bfloat16*)w1h, (__nv_bfloat16*)w1l, n4w1);
        split_fp32<<<(unsigned)((n4w2 + 255) / 256), 256>>>(W2, (__nv_bfloat16*)w2h, (__nv_bfloat16*)w2l, n4w2);
    }

    // tensor maps via driver entry point (no -lcuda link needed)
    PFN_tmap enc = nullptr;
    cudaDriverEntryPointQueryResult qr;
    cudaGetDriverEntryPoint("cuTensorMapEncodeTiled", (void**)&enc,
                            cudaEnableDefault, &qr);

    CUtensorMap m_xh128, m_xl128, m_xh64, m_xl64;
    CUtensorMap m_h1h64, m_h1l64, m_w1h, m_w1l, m_w2h, m_w2l;
    mk2d(enc, &m_xh128, xh,  DIN_, MB_,  128);
    mk2d(enc, &m_xl128, xl,  DIN_, MB_,  128);
    mk2d(enc, &m_xh64,  xh,  DIN_, MB_,  64);
    mk2d(enc, &m_xl64,  xl,  DIN_, MB_,  64);
    mk2d(enc, &m_h1h64, h1h, HID_, MB_,  64);
    mk2d(enc, &m_h1l64, h1l, HID_, MB_,  64);
    mk2d(enc, &m_w1h,   w1h, DIN_, HID_, 128);
    mk2d(enc, &m_w1l,   w1l, DIN_, HID_, 128);
    mk2d(enc, &m_w2h,   w2h, K2_,  ONN_, 128);
    mk2d(enc, &m_w2l,   w2l, K2_,  ONN_, 128);

    const int smem1 = STAGE0_OFF + NSTAGE * (2 * 128 * 128 + 32768);   // 197632
    const int smem2 = STAGE0_OFF + NSTAGE * (2 * 64  * 128 + 32768);   // 148480
    cudaFuncSetAttribute(gemm_hmma<0,128>, cudaFuncAttributeMaxDynamicSharedMemorySize, smem1);
    cudaFuncSetAttribute(gemm_hmma<1,64>,  cudaFuncAttributeMaxDynamicSharedMemorySize, smem2);

    // GEMM1: h1 = relu(x @ W1^T + b1); M-fastest grid for W1-band L2 reuse
    dim3 g1(MB_ / 128, HID_ / 128);   // (32, 128)
    gemm_hmma<0,128><<<g1, 256, smem1>>>(m_xh128, m_xl128, m_xh128, m_xl128,
                                         m_w1h, m_w1l, DIN_, 0, 0, b1, nullptr);

    // GEMM2: out = [x, h1] @ W2^T + b2  (64-row tiles -> 512 CTAs, less tail)
    dim3 g2(MB_ / 64, (ONN_ + 127) / 128);   // (64, 8)
    gemm_hmma<1,64><<<g2, 256, smem2>>>(m_xh64, m_xl64, m_h1h64, m_h1l64,
                                        m_w2h, m_w2l, DIN_, HID_, DIN_, b2, out);
}